// round 14
// baseline (speedup 1.0000x reference)
#include <cuda_runtime.h>
#include <cuda_fp16.h>

// Problem constants (fixed by the dataset)
#define MAXN 100000
#define MAXE 1600000
#define D 128
#define FIN 4
#define EPS 1e-5f
#define SCAN_T 512

// ---------------- scratch (static device globals; TOTAL = 33.2 MB, proven OK)
__device__ __half d_H[(size_t)MAXN * D];         // 25.6 MB fp16 feature buffer (dinv-prescaled)
__device__ int    d_csr[MAXE + MAXN];            //  6.8 MB CSR src indices
__device__ float  d_dinv[MAXN];                  //  0.4 MB
__device__ int    d_cur[MAXN];                   //  0.4 MB counts -> offsets -> ends
__device__ int    d_bsum[1024];
__device__ float  d_bnsum[D];
__device__ float  d_bnsq[D];
__device__ float  d_a[D];                        // BN scale (g * invstd)
__device__ float  d_c[D];                        // BN shift (be - mean*a)

// ---------------- preprocessing ---------------------------------------------
__global__ void k_init1(int n) {
    int i = blockIdx.x * blockDim.x + threadIdx.x;
    if (i < n) d_cur[i] = 1;                     // self loop
}

__global__ void k_count(const int* __restrict__ col, int e) {
    int i = blockIdx.x * blockDim.x + threadIdx.x;
    if (i < e) atomicAdd(&d_cur[col[i]], 1);
}

__global__ void k_dinv(int n) {
    int i = blockIdx.x * blockDim.x + threadIdx.x;
    if (i < n) d_dinv[i] = rsqrtf((float)d_cur[i]);
}

__global__ void k_blocksum(int n) {
    __shared__ int s[SCAN_T];
    int i = blockIdx.x * SCAN_T + threadIdx.x;
    s[threadIdx.x] = (i < n) ? d_cur[i] : 0;
    __syncthreads();
    for (int o = SCAN_T / 2; o > 0; o >>= 1) {
        if (threadIdx.x < o) s[threadIdx.x] += s[threadIdx.x + o];
        __syncthreads();
    }
    if (threadIdx.x == 0) d_bsum[blockIdx.x] = s[0];
}

__global__ void k_scan_bsum(int nb) {
    __shared__ int s[1024];
    int t = threadIdx.x;
    if (t < nb) s[t] = d_bsum[t];
    __syncthreads();
    if (t == 0) {
        int acc = 0;
        for (int i = 0; i < nb; i++) { int v = s[i]; s[i] = acc; acc += v; }
    }
    __syncthreads();
    if (t < nb) d_bsum[t] = s[t];
}

// in-place: counts -> exclusive offsets
__global__ void k_offsets(int n) {
    __shared__ int s[SCAN_T];
    int i = blockIdx.x * SCAN_T + threadIdx.x;
    int v = (i < n) ? d_cur[i] : 0;
    s[threadIdx.x] = v;
    __syncthreads();
    for (int o = 1; o < SCAN_T; o <<= 1) {
        int t = 0;
        if (threadIdx.x >= o) t = s[threadIdx.x - o];
        __syncthreads();
        s[threadIdx.x] += t;
        __syncthreads();
    }
    if (i < n) d_cur[i] = s[threadIdx.x] - v + d_bsum[blockIdx.x];
}

__global__ void k_fill(const int* __restrict__ row, const int* __restrict__ col, int e) {
    int i = blockIdx.x * blockDim.x + threadIdx.x;
    if (i < e) {
        int p = atomicAdd(&d_cur[col[i]], 1);
        d_csr[p] = row[i];
    }
}

__global__ void k_fillself(int n) {
    int i = blockIdx.x * blockDim.x + threadIdx.x;
    if (i < n) {
        int p = atomicAdd(&d_cur[i], 1);
        d_csr[p] = i;
    }
}
// after fill: d_cur[v] = end offset of node v; start = (v ? d_cur[v-1] : 0)

// ---------------- layer 1 GEMM (K = 4), writes dinv-scaled fp16 H ------------
__global__ void k_gemm1(const float* __restrict__ x, const float* __restrict__ W1, int n) {
    __shared__ float Ws[FIN][D];
    int t = threadIdx.x;                         // 64 threads; cols 2t, 2t+1
    #pragma unroll
    for (int k = 0; k < FIN; k++) {
        Ws[k][t] = W1[k * D + t];
        Ws[k][t + 64] = W1[k * D + t + 64];
    }
    __syncthreads();
    int c0 = t * 2, c1 = t * 2 + 1;
    for (int r = blockIdx.x; r < n; r += gridDim.x) {
        float4 xr = ((const float4*)x)[r];
        float dv = d_dinv[r];
        float v0 = xr.x * Ws[0][c0] + xr.y * Ws[1][c0] + xr.z * Ws[2][c0] + xr.w * Ws[3][c0];
        float v1 = xr.x * Ws[0][c1] + xr.y * Ws[1][c1] + xr.z * Ws[2][c1] + xr.w * Ws[3][c1];
        ((__half2*)(d_H + (size_t)r * D))[t] = __floats2half2_rn(v0 * dv, v1 * dv);
    }
}

__global__ void k_zero_bn() {
    int t = threadIdx.x;
    d_bnsum[t] = 0.f;
    d_bnsq[t]  = 0.f;
}

__global__ void k_bnfin(const float* __restrict__ g, const float* __restrict__ be, int n) {
    int t = threadIdx.x;                         // 128 threads
    float inv_n = 1.0f / (float)n;
    float m   = d_bnsum[t] * inv_n;
    float var = d_bnsq[t] * inv_n - m * m;
    float inv = rsqrtf(var + EPS);
    float a = g[t] * inv;
    d_a[t] = a;
    d_c[t] = be[t] - m * a;
}

// -------- BN+ReLU apply + dinv prescale + fp16 convert:  H = dinv*relu(bn(A))
__global__ void k_bnrelu_h(const float* __restrict__ A, int n) {
    int i = blockIdx.x * blockDim.x + threadIdx.x;   // one float4 each
    int total = n * (D / 4);
    if (i < total) {
        int dq = (i & 31) * 4;
        int rowi = i >> 5;
        float dv = d_dinv[rowi];
        float4 v = ((const float4*)A)[i];
        float r0 = fmaxf(fmaf(d_a[dq + 0], v.x, d_c[dq + 0]), 0.f) * dv;
        float r1 = fmaxf(fmaf(d_a[dq + 1], v.y, d_c[dq + 1]), 0.f) * dv;
        float r2 = fmaxf(fmaf(d_a[dq + 2], v.z, d_c[dq + 2]), 0.f) * dv;
        float r3 = fmaxf(fmaf(d_a[dq + 3], v.w, d_c[dq + 3]), 0.f) * dv;
        __half2 h0 = __floats2half2_rn(r0, r1);
        __half2 h1 = __floats2half2_rn(r2, r3);
        uint2 pk;
        pk.x = *(unsigned int*)&h0;
        pk.y = *(unsigned int*)&h1;
        ((uint2*)d_H)[i] = pk;
    }
}

// ---------------- full-width fp16 gather (MLP=4) + fused BN stats ------------
// A[v, :] = dinv[v] * sum_{s in N(v)} H[s, :]   (H pre-scaled by dinv[s])
__global__ void __launch_bounds__(256) k_gather(float* __restrict__ A, int doStats, int n) {
    __shared__ float ssum[D], ssq[D];
    int t = threadIdx.x, lane = t & 31, warp = t >> 5;
    if (doStats && t < D) { ssum[t] = 0.f; ssq[t] = 0.f; }
    __syncthreads();

    float4 rs = make_float4(0.f, 0.f, 0.f, 0.f);
    float4 rq = make_float4(0.f, 0.f, 0.f, 0.f);

    for (int v = blockIdx.x * 8 + warp; v < n; v += gridDim.x * 8) {
        int start = v ? d_cur[v - 1] : 0;
        int end   = d_cur[v];
        float dv  = d_dinv[v];
        float4 acc0 = make_float4(0.f, 0.f, 0.f, 0.f);
        float4 acc1 = make_float4(0.f, 0.f, 0.f, 0.f);
        float4 acc2 = make_float4(0.f, 0.f, 0.f, 0.f);
        float4 acc3 = make_float4(0.f, 0.f, 0.f, 0.f);
        int j = start;
        for (; j + 4 <= end; j += 4) {
            int s0 = d_csr[j];                              // warp-uniform bcast
            int s1 = d_csr[j + 1];
            int s2 = d_csr[j + 2];
            int s3 = d_csr[j + 3];
            uint2 p0 = __ldg((const uint2*)(d_H + (size_t)s0 * D) + lane);
            uint2 p1 = __ldg((const uint2*)(d_H + (size_t)s1 * D) + lane);
            uint2 p2 = __ldg((const uint2*)(d_H + (size_t)s2 * D) + lane);
            uint2 p3 = __ldg((const uint2*)(d_H + (size_t)s3 * D) + lane);
            float2 a0 = __half22float2(*(__half2*)&p0.x);
            float2 a1 = __half22float2(*(__half2*)&p0.y);
            float2 b0 = __half22float2(*(__half2*)&p1.x);
            float2 b1 = __half22float2(*(__half2*)&p1.y);
            float2 c0 = __half22float2(*(__half2*)&p2.x);
            float2 c1 = __half22float2(*(__half2*)&p2.y);
            float2 e0 = __half22float2(*(__half2*)&p3.x);
            float2 e1 = __half22float2(*(__half2*)&p3.y);
            acc0.x += a0.x; acc0.y += a0.y; acc0.z += a1.x; acc0.w += a1.y;
            acc1.x += b0.x; acc1.y += b0.y; acc1.z += b1.x; acc1.w += b1.y;
            acc2.x += c0.x; acc2.y += c0.y; acc2.z += c1.x; acc2.w += c1.y;
            acc3.x += e0.x; acc3.y += e0.y; acc3.z += e1.x; acc3.w += e1.y;
        }
        for (; j < end; j++) {
            int s0 = d_csr[j];
            uint2 p0 = __ldg((const uint2*)(d_H + (size_t)s0 * D) + lane);
            float2 a0 = __half22float2(*(__half2*)&p0.x);
            float2 a1 = __half22float2(*(__half2*)&p0.y);
            acc0.x += a0.x; acc0.y += a0.y; acc0.z += a1.x; acc0.w += a1.y;
        }
        float4 acc;
        acc.x = ((acc0.x + acc1.x) + (acc2.x + acc3.x)) * dv;
        acc.y = ((acc0.y + acc1.y) + (acc2.y + acc3.y)) * dv;
        acc.z = ((acc0.z + acc1.z) + (acc2.z + acc3.z)) * dv;
        acc.w = ((acc0.w + acc1.w) + (acc2.w + acc3.w)) * dv;
        ((float4*)(A + (size_t)v * D))[lane] = acc;
        if (doStats) {
            rs.x += acc.x; rs.y += acc.y; rs.z += acc.z; rs.w += acc.w;
            rq.x += acc.x * acc.x; rq.y += acc.y * acc.y;
            rq.z += acc.z * acc.z; rq.w += acc.w * acc.w;
        }
    }

    if (doStats) {
        int c = lane * 4;
        atomicAdd(&ssum[c + 0], rs.x); atomicAdd(&ssum[c + 1], rs.y);
        atomicAdd(&ssum[c + 2], rs.z); atomicAdd(&ssum[c + 3], rs.w);
        atomicAdd(&ssq [c + 0], rq.x); atomicAdd(&ssq [c + 1], rq.y);
        atomicAdd(&ssq [c + 2], rq.z); atomicAdd(&ssq [c + 3], rq.w);
        __syncthreads();
        if (t < D) {
            atomicAdd(&d_bnsum[t], ssum[t]);
            atomicAdd(&d_bnsq[t],  ssq[t]);
        }
    }
}

// ---------------- fp16 HMMA helpers ------------------------------------------
__device__ __forceinline__ void mma_f16(float& c0, float& c1, float& c2, float& c3,
                                        unsigned a0, unsigned a1, unsigned a2, unsigned a3,
                                        unsigned b0, unsigned b1) {
    asm("mma.sync.aligned.m16n8k16.row.col.f32.f16.f16.f32 "
        "{%0,%1,%2,%3}, {%4,%5,%6,%7}, {%8,%9}, {%0,%1,%2,%3};"
        : "+f"(c0), "+f"(c1), "+f"(c2), "+f"(c3)
        : "r"(a0), "r"(a1), "r"(a2), "r"(a3), "r"(b0), "r"(b1));
}

// ---------------- in-place fp16 GEMM on tensor cores (2xFP16 weight split) ----
// H[m, :] <- H[m, :] @ W  (W fp32, split hi+lo fp16; A operand exact fp16;
// fp32 accumulate; output rounded to fp16). Block owns 128 rows -> in-place safe.
__global__ void __launch_bounds__(256) k_gemm_h(const float* __restrict__ W, int n) {
    __shared__ __align__(16) __half As[128][136];    // 34.8 KB, pitch 136
    __shared__ __align__(16) __half Bh[128][18];     // n-major W-chunk hi
    __shared__ __align__(16) __half Bl[128][18];     // n-major W-chunk lo
    int t = threadIdx.x;
    int m0 = blockIdx.x * 128;

    // load whole A block (128 x 128 fp16), zero-fill rows >= n
    #pragma unroll
    for (int i = 0; i < 8; i++) {
        int f = t + i * 256;                 // 0..2047 uint4 units (8 halfs each)
        int r = f >> 4, q = f & 15;
        uint4 v = make_uint4(0u, 0u, 0u, 0u);
        int gm = m0 + r;
        if (gm < n) v = *(const uint4*)(d_H + (size_t)gm * D + q * 8);
        *(uint4*)&As[r][q * 8] = v;
    }

    int wid = t >> 5, lane = t & 31;
    int g = lane >> 2, tc = lane & 3;
    int wm = (wid & 1) * 64;                 // warp m offset (2 warps in m)
    int wn = (wid >> 1) * 32;                // warp n offset (4 warps in n)

    float acc[4][4][4];
    #pragma unroll
    for (int mt = 0; mt < 4; mt++)
        #pragma unroll
        for (int nt = 0; nt < 4; nt++)
            #pragma unroll
            for (int r = 0; r < 4; r++) acc[mt][nt][r] = 0.f;

    for (int kc = 0; kc < 8; kc++) {
        int k0 = kc * 16;
        __syncthreads();                     // A ready (iter 0) / prev B reads done
        // load W chunk [k0, k0+16) x 128 -> transposed n-major, split hi/lo
        #pragma unroll
        for (int i = 0; i < 8; i++) {
            int f = t + i * 256;             // 0..2047
            int kk = f >> 7, nn = f & 127;
            float w = W[(size_t)(k0 + kk) * D + nn];
            __half hi = __float2half_rn(w);
            __half lo = __float2half_rn(w - __half2float(hi));
            Bh[nn][kk] = hi;
            Bl[nn][kk] = lo;
        }
        __syncthreads();

        // A fragments per mt (shared across nt)
        unsigned afr[4][4];
        #pragma unroll
        for (int mt = 0; mt < 4; mt++) {
            int r0 = wm + mt * 16 + g;
            afr[mt][0] = *(const unsigned*)&As[r0][k0 + tc * 2];
            afr[mt][1] = *(const unsigned*)&As[r0 + 8][k0 + tc * 2];
            afr[mt][2] = *(const unsigned*)&As[r0][k0 + tc * 2 + 8];
            afr[mt][3] = *(const unsigned*)&As[r0 + 8][k0 + tc * 2 + 8];
        }
        #pragma unroll
        for (int nt = 0; nt < 4; nt++) {
            int cn = wn + nt * 8 + g;
            unsigned bh0 = *(const unsigned*)&Bh[cn][tc * 2];
            unsigned bh1 = *(const unsigned*)&Bh[cn][tc * 2 + 8];
            unsigned bl0 = *(const unsigned*)&Bl[cn][tc * 2];
            unsigned bl1 = *(const unsigned*)&Bl[cn][tc * 2 + 8];
            #pragma unroll
            for (int mt = 0; mt < 4; mt++) {
                mma_f16(acc[mt][nt][0], acc[mt][nt][1], acc[mt][nt][2], acc[mt][nt][3],
                        afr[mt][0], afr[mt][1], afr[mt][2], afr[mt][3], bl0, bl1);
                mma_f16(acc[mt][nt][0], acc[mt][nt][1], acc[mt][nt][2], acc[mt][nt][3],
                        afr[mt][0], afr[mt][1], afr[mt][2], afr[mt][3], bh0, bh1);
            }
        }
    }

    // in-place fp16 store: c0,c1 -> row g; c2,c3 -> row g+8 (cols 2tc, 2tc+1)
    #pragma unroll
    for (int mt = 0; mt < 4; mt++) {
        int r0 = m0 + wm + mt * 16 + g;
        int r1 = r0 + 8;
        #pragma unroll
        for (int nt = 0; nt < 4; nt++) {
            int cn = wn + nt * 8 + tc * 2;
            if (r0 < n) {
                __half2 h = __floats2half2_rn(acc[mt][nt][0], acc[mt][nt][1]);
                *(__half2*)(d_H + (size_t)r0 * D + cn) = h;
            }
            if (r1 < n) {
                __half2 h = __floats2half2_rn(acc[mt][nt][2], acc[mt][nt][3]);
                *(__half2*)(d_H + (size_t)r1 * D + cn) = h;
            }
        }
    }
}

// ---------------- final BN apply (in place) ----------------------------------
__global__ void k_apply(float* __restrict__ out, int n) {
    int i = blockIdx.x * blockDim.x + threadIdx.x;
    int total = n * (D / 4);
    if (i < total) {
        int dq = (i & 31) * 4;
        float4 v = ((const float4*)out)[i];
        float4 r;
        r.x = fmaf(d_a[dq + 0], v.x, d_c[dq + 0]);
        r.y = fmaf(d_a[dq + 1], v.y, d_c[dq + 1]);
        r.z = fmaf(d_a[dq + 2], v.z, d_c[dq + 2]);
        r.w = fmaf(d_a[dq + 3], v.w, d_c[dq + 3]);
        ((float4*)out)[i] = r;
    }
}

// ---------------- launch ------------------------------------------------------
extern "C" void kernel_launch(void* const* d_in, const int* in_sizes, int n_in,
                              void* d_out, int out_size) {
    const float* x   = (const float*)d_in[0];
    const int*   ei  = (const int*)  d_in[1];
    const float* W1  = (const float*)d_in[2];
    // d_in[3] = b1 (cancels under BN), skipped
    const float* g1  = (const float*)d_in[4];
    const float* be1 = (const float*)d_in[5];
    const float* Ws  = (const float*)d_in[6];   // [2,128,128]
    // d_in[7] = bs, skipped
    const float* gs  = (const float*)d_in[8];   // [2,128]
    const float* bes = (const float*)d_in[9];   // [2,128]
    float* A = (float*)d_out;                   // primary N x 128 fp32 buffer

    int n = in_sizes[0] / FIN;
    int e = in_sizes[1] / 2;
    const int* row = ei;
    const int* col = ei + e;
    int nb = (n + SCAN_T - 1) / SCAN_T;
    int total4 = n * (D / 4);
    int cb = (total4 + 255) / 256;

    // -- preprocessing: degrees -> dinv -> CSR offsets -> fill
    k_init1<<<(n + 255) / 256, 256>>>(n);
    k_count<<<(e + 255) / 256, 256>>>(col, e);
    k_dinv<<<(n + 255) / 256, 256>>>(n);
    k_blocksum<<<nb, SCAN_T>>>(n);
    k_scan_bsum<<<1, 1024>>>(nb);
    k_offsets<<<nb, SCAN_T>>>(n);
    k_fill<<<(e + 255) / 256, 256>>>(row, col, e);
    k_fillself<<<(n + 255) / 256, 256>>>(n);

    int gb = (n + 127) / 128;

    // -- layer 1: H = fp16(dinv * (x @ W1));  z1 = Ahat_scaled @ H -> A (BN1 stats)
    k_gemm1<<<2048, 64>>>(x, W1, n);
    k_zero_bn<<<1, D>>>();
    k_gather<<<2048, 256>>>(A, 1, n);
    k_bnfin<<<1, D>>>(g1, be1, n);

    // -- layer 2: H = fp16(dinv*relu(bn1(z1)));  H = H @ W2 (HMMA, in-place);
    //             z2 = gather(H) -> A (BN2 stats)
    k_bnrelu_h<<<cb, 256>>>(A, n);
    k_gemm_h<<<gb, 256>>>(Ws, n);
    k_zero_bn<<<1, D>>>();
    k_gather<<<2048, 256>>>(A, 1, n);
    k_bnfin<<<1, D>>>(gs, bes, n);

    // -- layer 3: same with W3
    k_bnrelu_h<<<cb, 256>>>(A, n);
    k_gemm_h<<<gb, 256>>>(Ws + D * D, n);
    k_zero_bn<<<1, D>>>();
    k_gather<<<2048, 256>>>(A, 1, n);
    k_bnfin<<<1, D>>>(gs + D, bes + D, n);

    // -- final BN apply in place
    k_apply<<<cb, 256>>>(A, n);
}

// round 15
// speedup vs baseline: 1.0565x; 1.0565x over previous
#include <cuda_runtime.h>
#include <cuda_fp16.h>

// Problem constants (fixed by the dataset)
#define MAXN 100000
#define MAXE 1600000
#define D 128
#define FIN 4
#define EPS 1e-5f
#define SCAN_T 512

// ---------------- scratch (static device globals; TOTAL = 33.2 MB, proven OK)
__device__ __half d_H[(size_t)MAXN * D];         // 25.6 MB fp16 feature buffer (dinv-prescaled)
__device__ int    d_csr[MAXE + MAXN];            //  6.8 MB CSR src indices
__device__ float  d_dinv[MAXN];                  //  0.4 MB
__device__ int    d_cur[MAXN];                   //  0.4 MB counts -> offsets -> ends
__device__ int    d_bsum[1024];
__device__ float  d_bnsum[D];
__device__ float  d_bnsq[D];
__device__ float  d_a[D];                        // BN scale (g * invstd)
__device__ float  d_c[D];                        // BN shift (be - mean*a)

// ---------------- preprocessing ---------------------------------------------
// d_cur starts zeroed (memsetAsync); k_count accumulates raw in-degree.
// Degree including self-loop = d_cur[i] + 1 (applied algebraically below).
__global__ void k_count(const int* __restrict__ col, int e) {
    int i = blockIdx.x * blockDim.x + threadIdx.x;
    if (i < e) atomicAdd(&d_cur[col[i]], 1);
}

// block-sum of (cnt+1) AND dinv = rsqrt(cnt+1), fused
__global__ void k_blocksum_dinv(int n) {
    __shared__ int s[SCAN_T];
    int i = blockIdx.x * SCAN_T + threadIdx.x;
    int v = 0;
    if (i < n) {
        int deg = d_cur[i] + 1;
        d_dinv[i] = rsqrtf((float)deg);
        v = deg;
    }
    s[threadIdx.x] = v;
    __syncthreads();
    for (int o = SCAN_T / 2; o > 0; o >>= 1) {
        if (threadIdx.x < o) s[threadIdx.x] += s[threadIdx.x + o];
        __syncthreads();
    }
    if (threadIdx.x == 0) d_bsum[blockIdx.x] = s[0];
}

__global__ void k_scan_bsum(int nb) {
    __shared__ int s[1024];
    int t = threadIdx.x;
    if (t < nb) s[t] = d_bsum[t];
    __syncthreads();
    if (t == 0) {
        int acc = 0;
        for (int i = 0; i < nb; i++) { int v = s[i]; s[i] = acc; acc += v; }
    }
    __syncthreads();
    if (t < nb) d_bsum[t] = s[t];
}

// in-place: counts -> exclusive offsets of (cnt+1)
__global__ void k_offsets(int n) {
    __shared__ int s[SCAN_T];
    int i = blockIdx.x * SCAN_T + threadIdx.x;
    int v = (i < n) ? d_cur[i] + 1 : 0;
    s[threadIdx.x] = v;
    __syncthreads();
    for (int o = 1; o < SCAN_T; o <<= 1) {
        int t = 0;
        if (threadIdx.x >= o) t = s[threadIdx.x - o];
        __syncthreads();
        s[threadIdx.x] += t;
        __syncthreads();
    }
    if (i < n) d_cur[i] = s[threadIdx.x] - v + d_bsum[blockIdx.x];
}

__global__ void k_fill(const int* __restrict__ row, const int* __restrict__ col, int e) {
    int i = blockIdx.x * blockDim.x + threadIdx.x;
    if (i < e) {
        int p = atomicAdd(&d_cur[col[i]], 1);
        d_csr[p] = row[i];
    }
}

__global__ void k_fillself(int n) {
    int i = blockIdx.x * blockDim.x + threadIdx.x;
    if (i < n) {
        int p = atomicAdd(&d_cur[i], 1);
        d_csr[p] = i;
    }
}
// after fill: d_cur[v] = end offset of node v; start = (v ? d_cur[v-1] : 0)

// ---------------- layer 1 GEMM (K = 4), writes dinv-scaled fp16 H ------------
__global__ void k_gemm1(const float* __restrict__ x, const float* __restrict__ W1, int n) {
    __shared__ float Ws[FIN][D];
    int t = threadIdx.x;                         // 64 threads; cols 2t, 2t+1
    #pragma unroll
    for (int k = 0; k < FIN; k++) {
        Ws[k][t] = W1[k * D + t];
        Ws[k][t + 64] = W1[k * D + t + 64];
    }
    __syncthreads();
    int c0 = t * 2, c1 = t * 2 + 1;
    for (int r = blockIdx.x; r < n; r += gridDim.x) {
        float4 xr = ((const float4*)x)[r];
        float dv = d_dinv[r];
        float v0 = xr.x * Ws[0][c0] + xr.y * Ws[1][c0] + xr.z * Ws[2][c0] + xr.w * Ws[3][c0];
        float v1 = xr.x * Ws[0][c1] + xr.y * Ws[1][c1] + xr.z * Ws[2][c1] + xr.w * Ws[3][c1];
        ((__half2*)(d_H + (size_t)r * D))[t] = __floats2half2_rn(v0 * dv, v1 * dv);
    }
}

__global__ void k_zero_bn() {
    int t = threadIdx.x;
    d_bnsum[t] = 0.f;
    d_bnsq[t]  = 0.f;
}

// bnfin consumes stats, emits a/c, and re-zeroes stats for the next layer.
__global__ void k_bnfin(const float* __restrict__ g, const float* __restrict__ be, int n) {
    int t = threadIdx.x;                         // 128 threads
    float inv_n = 1.0f / (float)n;
    float m   = d_bnsum[t] * inv_n;
    float var = d_bnsq[t] * inv_n - m * m;
    float inv = rsqrtf(var + EPS);
    float a = g[t] * inv;
    d_a[t] = a;
    d_c[t] = be[t] - m * a;
    d_bnsum[t] = 0.f;
    d_bnsq[t]  = 0.f;
}

// ---------------- full-width fp16 gather + fused BN stats --------------------
// A[v, :] = dinv[v] * sum_{s in N(v)} H[s, :]   (H pre-scaled by dinv[s])
__global__ void __launch_bounds__(256) k_gather(float* __restrict__ A, int n) {
    __shared__ float ssum[D], ssq[D];
    int t = threadIdx.x, lane = t & 31, warp = t >> 5;
    if (t < D) { ssum[t] = 0.f; ssq[t] = 0.f; }
    __syncthreads();

    float4 rs = make_float4(0.f, 0.f, 0.f, 0.f);
    float4 rq = make_float4(0.f, 0.f, 0.f, 0.f);

    for (int v = blockIdx.x * 8 + warp; v < n; v += gridDim.x * 8) {
        int start = v ? d_cur[v - 1] : 0;
        int end   = d_cur[v];
        float dv  = d_dinv[v];
        float4 acc0 = make_float4(0.f, 0.f, 0.f, 0.f);
        float4 acc1 = make_float4(0.f, 0.f, 0.f, 0.f);
        int j = start;
        for (; j + 2 <= end; j += 2) {
            int s0 = d_csr[j];                              // warp-uniform bcast
            int s1 = d_csr[j + 1];
            uint2 pa = __ldg((const uint2*)(d_H + (size_t)s0 * D) + lane);
            uint2 pb = __ldg((const uint2*)(d_H + (size_t)s1 * D) + lane);
            float2 a0 = __half22float2(*(__half2*)&pa.x);
            float2 a1 = __half22float2(*(__half2*)&pa.y);
            float2 b0 = __half22float2(*(__half2*)&pb.x);
            float2 b1 = __half22float2(*(__half2*)&pb.y);
            acc0.x += a0.x; acc0.y += a0.y; acc0.z += a1.x; acc0.w += a1.y;
            acc1.x += b0.x; acc1.y += b0.y; acc1.z += b1.x; acc1.w += b1.y;
        }
        if (j < end) {
            int s0 = d_csr[j];
            uint2 pa = __ldg((const uint2*)(d_H + (size_t)s0 * D) + lane);
            float2 a0 = __half22float2(*(__half2*)&pa.x);
            float2 a1 = __half22float2(*(__half2*)&pa.y);
            acc0.x += a0.x; acc0.y += a0.y; acc0.z += a1.x; acc0.w += a1.y;
        }
        float4 acc;
        acc.x = (acc0.x + acc1.x) * dv;
        acc.y = (acc0.y + acc1.y) * dv;
        acc.z = (acc0.z + acc1.z) * dv;
        acc.w = (acc0.w + acc1.w) * dv;
        ((float4*)(A + (size_t)v * D))[lane] = acc;
        rs.x += acc.x; rs.y += acc.y; rs.z += acc.z; rs.w += acc.w;
        rq.x += acc.x * acc.x; rq.y += acc.y * acc.y;
        rq.z += acc.z * acc.z; rq.w += acc.w * acc.w;
    }

    int c = lane * 4;
    atomicAdd(&ssum[c + 0], rs.x); atomicAdd(&ssum[c + 1], rs.y);
    atomicAdd(&ssum[c + 2], rs.z); atomicAdd(&ssum[c + 3], rs.w);
    atomicAdd(&ssq [c + 0], rq.x); atomicAdd(&ssq [c + 1], rq.y);
    atomicAdd(&ssq [c + 2], rq.z); atomicAdd(&ssq [c + 3], rq.w);
    __syncthreads();
    if (t < D) {
        atomicAdd(&d_bnsum[t], ssum[t]);
        atomicAdd(&d_bnsq[t],  ssq[t]);
    }
}

// ---------------- fp16 HMMA helpers ------------------------------------------
__device__ __forceinline__ void mma_f16(float& c0, float& c1, float& c2, float& c3,
                                        unsigned a0, unsigned a1, unsigned a2, unsigned a3,
                                        unsigned b0, unsigned b1) {
    asm("mma.sync.aligned.m16n8k16.row.col.f32.f16.f16.f32 "
        "{%0,%1,%2,%3}, {%4,%5,%6,%7}, {%8,%9}, {%0,%1,%2,%3};"
        : "+f"(c0), "+f"(c1), "+f"(c2), "+f"(c3)
        : "r"(a0), "r"(a1), "r"(a2), "r"(a3), "r"(b0), "r"(b1));
}

// ------ fused BN+ReLU+dinv + fp16 GEMM (2xFP16 weight split), writes H -------
// H[m, :] = (dinv[m] * relu(bn(A[m, :]))) @ W
// A fp32 read + BN applied inline during the smem A-tile build; fp32 accumulate;
// output rounded to fp16 into d_H. Identical rounding points to the previous
// separate-kernel pipeline.
__global__ void __launch_bounds__(256) k_gemm_bnr(const float* __restrict__ A,
                                                  const float* __restrict__ W, int n) {
    __shared__ __align__(16) __half As[128][136];    // 34.8 KB, pitch 136
    __shared__ __align__(16) __half Bh[128][18];     // n-major W-chunk hi
    __shared__ __align__(16) __half Bl[128][18];     // n-major W-chunk lo
    __shared__ float sa[D], sc[D];
    int t = threadIdx.x;
    int m0 = blockIdx.x * 128;

    if (t < D) { sa[t] = d_a[t]; sc[t] = d_c[t]; }
    __syncthreads();

    // build A tile: 128 rows x 128 cols, bn+relu+dinv applied, fp16 in smem
    #pragma unroll
    for (int i = 0; i < 8; i++) {
        int f = t + i * 256;                 // 0..2047; 8 halfs each
        int r = f >> 4, q = f & 15;          // row, col-group (8 cols)
        int gm = m0 + r;
        uint4 pk = make_uint4(0u, 0u, 0u, 0u);
        if (gm < n) {
            int cb = q * 8;
            float dv = d_dinv[gm];
            float4 v0 = *(const float4*)(A + (size_t)gm * D + cb);
            float4 v1 = *(const float4*)(A + (size_t)gm * D + cb + 4);
            float r0 = fmaxf(fmaf(sa[cb + 0], v0.x, sc[cb + 0]), 0.f) * dv;
            float r1 = fmaxf(fmaf(sa[cb + 1], v0.y, sc[cb + 1]), 0.f) * dv;
            float r2 = fmaxf(fmaf(sa[cb + 2], v0.z, sc[cb + 2]), 0.f) * dv;
            float r3 = fmaxf(fmaf(sa[cb + 3], v0.w, sc[cb + 3]), 0.f) * dv;
            float r4 = fmaxf(fmaf(sa[cb + 4], v1.x, sc[cb + 4]), 0.f) * dv;
            float r5 = fmaxf(fmaf(sa[cb + 5], v1.y, sc[cb + 5]), 0.f) * dv;
            float r6 = fmaxf(fmaf(sa[cb + 6], v1.z, sc[cb + 6]), 0.f) * dv;
            float r7 = fmaxf(fmaf(sa[cb + 7], v1.w, sc[cb + 7]), 0.f) * dv;
            __half2 h0 = __floats2half2_rn(r0, r1);
            __half2 h1 = __floats2half2_rn(r2, r3);
            __half2 h2 = __floats2half2_rn(r4, r5);
            __half2 h3 = __floats2half2_rn(r6, r7);
            pk.x = *(unsigned*)&h0;
            pk.y = *(unsigned*)&h1;
            pk.z = *(unsigned*)&h2;
            pk.w = *(unsigned*)&h3;
        }
        *(uint4*)&As[r][q * 8] = pk;
    }

    int wid = t >> 5, lane = t & 31;
    int g = lane >> 2, tc = lane & 3;
    int wm = (wid & 1) * 64;                 // warp m offset (2 warps in m)
    int wn = (wid >> 1) * 32;                // warp n offset (4 warps in n)

    float acc[4][4][4];
    #pragma unroll
    for (int mt = 0; mt < 4; mt++)
        #pragma unroll
        for (int nt = 0; nt < 4; nt++)
            #pragma unroll
            for (int r = 0; r < 4; r++) acc[mt][nt][r] = 0.f;

    for (int kc = 0; kc < 8; kc++) {
        int k0 = kc * 16;
        __syncthreads();                     // A ready (iter 0) / prev B reads done
        // load W chunk [k0, k0+16) x 128 -> transposed n-major, split hi/lo
        #pragma unroll
        for (int i = 0; i < 8; i++) {
            int f = t + i * 256;             // 0..2047
            int kk = f >> 7, nn = f & 127;
            float w = W[(size_t)(k0 + kk) * D + nn];
            __half hi = __float2half_rn(w);
            __half lo = __float2half_rn(w - __half2float(hi));
            Bh[nn][kk] = hi;
            Bl[nn][kk] = lo;
        }
        __syncthreads();

        // A fragments per mt (shared across nt)
        unsigned afr[4][4];
        #pragma unroll
        for (int mt = 0; mt < 4; mt++) {
            int r0 = wm + mt * 16 + g;
            afr[mt][0] = *(const unsigned*)&As[r0][k0 + tc * 2];
            afr[mt][1] = *(const unsigned*)&As[r0 + 8][k0 + tc * 2];
            afr[mt][2] = *(const unsigned*)&As[r0][k0 + tc * 2 + 8];
            afr[mt][3] = *(const unsigned*)&As[r0 + 8][k0 + tc * 2 + 8];
        }
        #pragma unroll
        for (int nt = 0; nt < 4; nt++) {
            int cn = wn + nt * 8 + g;
            unsigned bh0 = *(const unsigned*)&Bh[cn][tc * 2];
            unsigned bh1 = *(const unsigned*)&Bh[cn][tc * 2 + 8];
            unsigned bl0 = *(const unsigned*)&Bl[cn][tc * 2];
            unsigned bl1 = *(const unsigned*)&Bl[cn][tc * 2 + 8];
            #pragma unroll
            for (int mt = 0; mt < 4; mt++) {
                mma_f16(acc[mt][nt][0], acc[mt][nt][1], acc[mt][nt][2], acc[mt][nt][3],
                        afr[mt][0], afr[mt][1], afr[mt][2], afr[mt][3], bl0, bl1);
                mma_f16(acc[mt][nt][0], acc[mt][nt][1], acc[mt][nt][2], acc[mt][nt][3],
                        afr[mt][0], afr[mt][1], afr[mt][2], afr[mt][3], bh0, bh1);
            }
        }
    }

    // fp16 store to H: c0,c1 -> row g; c2,c3 -> row g+8 (cols 2tc, 2tc+1)
    #pragma unroll
    for (int mt = 0; mt < 4; mt++) {
        int r0 = m0 + wm + mt * 16 + g;
        int r1 = r0 + 8;
        #pragma unroll
        for (int nt = 0; nt < 4; nt++) {
            int cn = wn + nt * 8 + tc * 2;
            if (r0 < n) {
                __half2 h = __floats2half2_rn(acc[mt][nt][0], acc[mt][nt][1]);
                *(__half2*)(d_H + (size_t)r0 * D + cn) = h;
            }
            if (r1 < n) {
                __half2 h = __floats2half2_rn(acc[mt][nt][2], acc[mt][nt][3]);
                *(__half2*)(d_H + (size_t)r1 * D + cn) = h;
            }
        }
    }
}

// ---------------- final BN apply (in place) ----------------------------------
__global__ void k_apply(float* __restrict__ out, int n) {
    int i = blockIdx.x * blockDim.x + threadIdx.x;
    int total = n * (D / 4);
    if (i < total) {
        int dq = (i & 31) * 4;
        float4 v = ((const float4*)out)[i];
        float4 r;
        r.x = fmaf(d_a[dq + 0], v.x, d_c[dq + 0]);
        r.y = fmaf(d_a[dq + 1], v.y, d_c[dq + 1]);
        r.z = fmaf(d_a[dq + 2], v.z, d_c[dq + 2]);
        r.w = fmaf(d_a[dq + 3], v.w, d_c[dq + 3]);
        ((float4*)out)[i] = r;
    }
}

// ---------------- launch ------------------------------------------------------
extern "C" void kernel_launch(void* const* d_in, const int* in_sizes, int n_in,
                              void* d_out, int out_size) {
    const float* x   = (const float*)d_in[0];
    const int*   ei  = (const int*)  d_in[1];
    const float* W1  = (const float*)d_in[2];
    // d_in[3] = b1 (cancels under BN), skipped
    const float* g1  = (const float*)d_in[4];
    const float* be1 = (const float*)d_in[5];
    const float* Ws  = (const float*)d_in[6];   // [2,128,128]
    // d_in[7] = bs, skipped
    const float* gs  = (const float*)d_in[8];   // [2,128]
    const float* bes = (const float*)d_in[9];   // [2,128]
    float* A = (float*)d_out;                   // primary N x 128 fp32 buffer

    int n = in_sizes[0] / FIN;
    int e = in_sizes[1] / 2;
    const int* row = ei;
    const int* col = ei + e;
    int nb = (n + SCAN_T - 1) / SCAN_T;
    int total4 = n * (D / 4);
    int cb = (total4 + 255) / 256;

    int* curp = nullptr;
    cudaGetSymbolAddress((void**)&curp, d_cur);

    // -- preprocessing: zero counts -> count -> dinv+blocksum -> scan -> offsets -> fill
    cudaMemsetAsync(curp, 0, (size_t)n * sizeof(int));
    k_count<<<(e + 255) / 256, 256>>>(col, e);
    k_blocksum_dinv<<<nb, SCAN_T>>>(n);
    k_scan_bsum<<<1, 1024>>>(nb);
    k_offsets<<<nb, SCAN_T>>>(n);
    k_fill<<<(e + 255) / 256, 256>>>(row, col, e);
    k_fillself<<<(n + 255) / 256, 256>>>(n);

    int gb = (n + 127) / 128;

    // -- layer 1: H = fp16(dinv * (x @ W1));  z1 = gather(H) -> A (BN1 stats)
    k_gemm1<<<2048, 64>>>(x, W1, n);
    k_zero_bn<<<1, D>>>();                       // establish stats invariant
    k_gather<<<2048, 256>>>(A, n);
    k_bnfin<<<1, D>>>(g1, be1, n);               // also zeroes stats

    // -- layer 2: H = (dinv*relu(bn1(A))) @ W2 (fused HMMA);  z2 = gather(H) -> A
    k_gemm_bnr<<<gb, 256>>>(A, Ws, n);
    k_gather<<<2048, 256>>>(A, n);
    k_bnfin<<<1, D>>>(gs, bes, n);

    // -- layer 3: same with W3
    k_gemm_bnr<<<gb, 256>>>(A, Ws + D * D, n);
    k_gather<<<2048, 256>>>(A, n);
    k_bnfin<<<1, D>>>(gs + D, bes + D, n);

    // -- final BN apply in place
    k_apply<<<cb, 256>>>(A, n);
}